// round 17
// baseline (speedup 1.0000x reference)
#include <cuda_runtime.h>
#include <cuda_fp16.h>
#include <stdint.h>

#define NN 50000
#define EE 400000
#define HH 512
#define OO 256
#define KK 512
#define BN_EPS 1e-5f

#define BM 128
#define BNT 128          // N tile
#define NCH 16           // 16 chunks of K=32, single fp16 term

// ---------------- scratch (device globals) ----------------
__device__ __align__(256) __half g_Y[(size_t)NN * HH];           // fp16 pre-BN gemm2 out
__device__ __align__(256) __half g_Eh[(size_t)NN * KK];          // fp16(emb)
__device__ __align__(256) __half g_Sh[(size_t)NN * KK];          // fp16(S)
__device__ __align__(256) __half g_Hh[(size_t)NN * HH];          // fp16(relu(gemm1))
__device__ __align__(256) __half g_Wh[3][KK * HH];               // w1 fp16 [N][K]
__device__ __align__(256) __half g_Vh[3][KK * HH];               // w2 fp16 [N][K]
__device__ int   g_rowptr[NN + 1];
__device__ int   g_cnt[NN];
__device__ int   g_cnt2[NN];
__device__ int   g_colidx[EE];
__device__ float g_stats[2][2 * HH];                             // per-layer col sums / sumsq

// ---------------- PTX helpers (sm_80-level, sm_100-safe) ----------------
__device__ __forceinline__ uint32_t smem_u32(const void* p) {
    uint32_t a;
    asm("{ .reg .u64 t; cvta.to.shared.u64 t, %1; cvt.u32.u64 %0, t; }" : "=r"(a) : "l"(p));
    return a;
}
__device__ __forceinline__ uint32_t sw64(uint32_t b) { return b ^ ((b >> 3) & 0x30); }

__device__ __forceinline__ void cpa16(uint32_t dst, const void* src, bool pred) {
    int sz = pred ? 16 : 0;
    asm volatile("cp.async.cg.shared.global [%0], [%1], 16, %2;"
                 :: "r"(dst), "l"(src), "r"(sz) : "memory");
}
__device__ __forceinline__ void cpa_commit() {
    asm volatile("cp.async.commit_group;" ::: "memory");
}
template <int N>
__device__ __forceinline__ void cpa_wait() {
    asm volatile("cp.async.wait_group %0;" :: "n"(N) : "memory");
}
__device__ __forceinline__ void ldmx4(uint32_t* r, uint32_t addr) {
    asm volatile("ldmatrix.sync.aligned.m8n8.x4.shared.b16 {%0,%1,%2,%3}, [%4];"
                 : "=r"(r[0]), "=r"(r[1]), "=r"(r[2]), "=r"(r[3]) : "r"(addr));
}
__device__ __forceinline__ void mma16816(float* c, const uint32_t* a, const uint32_t* b) {
    asm volatile(
        "mma.sync.aligned.m16n8k16.row.col.f32.f16.f16.f32 "
        "{%0,%1,%2,%3},{%4,%5,%6,%7},{%8,%9},{%0,%1,%2,%3};"
        : "+f"(c[0]), "+f"(c[1]), "+f"(c[2]), "+f"(c[3])
        : "r"(a[0]), "r"(a[1]), "r"(a[2]), "r"(a[3]), "r"(b[0]), "r"(b[1]));
}

// half4 <-> float4
__device__ __forceinline__ float4 ld_h4(const __half* p) {
    uint2 v = *(const uint2*)p;
    __half2 h0 = *(__half2*)&v.x;
    __half2 h1 = *(__half2*)&v.y;
    float2 f0 = __half22float2(h0);
    float2 f1 = __half22float2(h1);
    return make_float4(f0.x, f0.y, f1.x, f1.y);
}
__device__ __forceinline__ uint2 pack_h4(const float4& f) {
    __half2 h0 = __floats2half2_rn(f.x, f.y);
    __half2 h1 = __floats2half2_rn(f.z, f.w);
    uint2 v;
    v.x = *(uint32_t*)&h0;
    v.y = *(uint32_t*)&h1;
    return v;
}

// ---------------- combined zero: counters + both stats buffers ----------------
__global__ void zero_all_k() {
    int i = blockIdx.x * blockDim.x + threadIdx.x;
    if (i < NN) { g_cnt[i] = 0; g_cnt2[i] = 0; }
    if (i < 2 * HH) { g_stats[0][i] = 0.f; g_stats[1][i] = 0.f; }
}

// ---------------- CSR build ----------------
__global__ void count_deg_k(const int* __restrict__ ei) {
    int e = blockIdx.x * blockDim.x + threadIdx.x;
    if (e < EE) atomicAdd(&g_cnt[__ldg(ei + EE + e)], 1);
}
__global__ void scan_k() {
    __shared__ int sm[1024];
    int t = threadIdx.x;
    const int CH = (NN + 1023) / 1024;
    int base = t * CH;
    int s = 0;
    for (int i = 0; i < CH; i++) {
        int idx = base + i;
        if (idx < NN) s += g_cnt[idx];
    }
    sm[t] = s;
    __syncthreads();
    for (int off = 1; off < 1024; off <<= 1) {
        int v = 0;
        if (t >= off) v = sm[t - off];
        __syncthreads();
        if (t >= off) sm[t] += v;
        __syncthreads();
    }
    int run = (t == 0) ? 0 : sm[t - 1];
    for (int i = 0; i < CH; i++) {
        int idx = base + i;
        if (idx < NN) {
            g_rowptr[idx] = run;
            run += g_cnt[idx];
        }
    }
    if (t == 1023) g_rowptr[NN] = run;
}
__global__ void fill_col_k(const int* __restrict__ ei) {
    int e = blockIdx.x * blockDim.x + threadIdx.x;
    if (e < EE) {
        int dst = __ldg(ei + EE + e);
        int pos = g_rowptr[dst] + atomicAdd(&g_cnt2[dst], 1);
        g_colidx[pos] = __ldg(ei + e);
    }
}

// ---------------- emb -> fp16 ----------------
__global__ void conv_emb_k(const float* __restrict__ emb) {
    size_t i = (size_t)blockIdx.x * blockDim.x + threadIdx.x;
    if (i >= (size_t)NN * KK / 4) return;
    float4 v = *(const float4*)(emb + i * 4);
    *(uint2*)(g_Eh + i * 4) = pack_h4(v);
}

// ---------------- fused aggregation ----------------
__device__ __forceinline__ void store_h4S(int node, int c, const float4& acc) {
    *(uint2*)(g_Sh + (size_t)node * KK + c) = pack_h4(acc);
}

// layer 0: S = E[xi[node]] + sum E[xi[src]]  (E = fp16 emb)
__global__ void agg_emb_k(const int* __restrict__ xi) {
    __shared__ int snb[128];
    int node = blockIdx.x;
    int tid = threadIdx.x;
    int c = tid << 2;
    float4 acc = ld_h4(g_Eh + (size_t)__ldg(xi + node) * KK + c);
    float4 acc2 = make_float4(0.f, 0.f, 0.f, 0.f);
    int ps = g_rowptr[node], pe = g_rowptr[node + 1];
    for (int base = ps; base < pe; base += 128) {
        int n = min(128, pe - base);
        __syncthreads();
        if (tid < n) snb[tid] = __ldg(xi + __ldg(g_colidx + base + tid));
        __syncthreads();
        int j = 0;
        for (; j + 1 < n; j += 2) {
            float4 v0 = ld_h4(g_Eh + (size_t)snb[j] * KK + c);
            float4 v1 = ld_h4(g_Eh + (size_t)snb[j + 1] * KK + c);
            acc.x += v0.x; acc.y += v0.y; acc.z += v0.z; acc.w += v0.w;
            acc2.x += v1.x; acc2.y += v1.y; acc2.z += v1.z; acc2.w += v1.w;
        }
        if (j < n) {
            float4 v = ld_h4(g_Eh + (size_t)snb[j] * KK + c);
            acc.x += v.x; acc.y += v.y; acc.z += v.z; acc.w += v.w;
        }
    }
    acc.x += acc2.x; acc.y += acc2.y; acc.z += acc2.z; acc.w += acc2.w;
    store_h4S(node, c, acc);
}

// layers 1,2: BN scale/shift computed in-block from stats; x = relu(bn(Y)); S = x[node] + sum x[src]
__global__ void agg_bn_k(const float* __restrict__ stats,
                         const float* __restrict__ gam, const float* __restrict__ bet) {
    __shared__ int snb[128];
    int node = blockIdx.x;
    int tid = threadIdx.x;
    int c = tid << 2;
    // per-thread BN fold (deterministic, identical across blocks)
    float4 sc, sh;
    {
        float* scp = (float*)&sc;
        float* shp = (float*)&sh;
#pragma unroll
        for (int e = 0; e < 4; e++) {
            float mu = __ldg(stats + c + e) * (1.f / NN);
            float var = __ldg(stats + HH + c + e) * (1.f / NN) - mu * mu;
            float s = rsqrtf(var + BN_EPS) * __ldg(gam + c + e);
            scp[e] = s;
            shp[e] = __ldg(bet + c + e) - mu * s;
        }
    }
    float4 y = ld_h4(g_Y + (size_t)node * HH + c);
    float4 acc;
    acc.x = fmaxf(fmaf(y.x, sc.x, sh.x), 0.f);
    acc.y = fmaxf(fmaf(y.y, sc.y, sh.y), 0.f);
    acc.z = fmaxf(fmaf(y.z, sc.z, sh.z), 0.f);
    acc.w = fmaxf(fmaf(y.w, sc.w, sh.w), 0.f);
    float4 acc2 = make_float4(0.f, 0.f, 0.f, 0.f);
    int ps = g_rowptr[node], pe = g_rowptr[node + 1];
    for (int base = ps; base < pe; base += 128) {
        int n = min(128, pe - base);
        __syncthreads();
        if (tid < n) snb[tid] = __ldg(g_colidx + base + tid);
        __syncthreads();
        int j = 0;
        for (; j + 1 < n; j += 2) {
            float4 v0 = ld_h4(g_Y + (size_t)snb[j] * HH + c);
            float4 v1 = ld_h4(g_Y + (size_t)snb[j + 1] * HH + c);
            acc.x += fmaxf(fmaf(v0.x, sc.x, sh.x), 0.f);
            acc.y += fmaxf(fmaf(v0.y, sc.y, sh.y), 0.f);
            acc.z += fmaxf(fmaf(v0.z, sc.z, sh.z), 0.f);
            acc.w += fmaxf(fmaf(v0.w, sc.w, sh.w), 0.f);
            acc2.x += fmaxf(fmaf(v1.x, sc.x, sh.x), 0.f);
            acc2.y += fmaxf(fmaf(v1.y, sc.y, sh.y), 0.f);
            acc2.z += fmaxf(fmaf(v1.z, sc.z, sh.z), 0.f);
            acc2.w += fmaxf(fmaf(v1.w, sc.w, sh.w), 0.f);
        }
        if (j < n) {
            float4 v = ld_h4(g_Y + (size_t)snb[j] * HH + c);
            acc.x += fmaxf(fmaf(v.x, sc.x, sh.x), 0.f);
            acc.y += fmaxf(fmaf(v.y, sc.y, sh.y), 0.f);
            acc.z += fmaxf(fmaf(v.z, sc.z, sh.z), 0.f);
            acc.w += fmaxf(fmaf(v.w, sc.w, sh.w), 0.f);
        }
    }
    acc.x += acc2.x; acc.y += acc2.y; acc.z += acc2.z; acc.w += acc2.w;
    store_h4S(node, c, acc);
}

// ---------------- all weight transposes in ONE launch ----------------
__global__ void wsplit_all_k(const float* w0, const float* w1, const float* w2,
                             const float* w3, const float* w4, const float* w5) {
    __shared__ float t[32][33];
    int z = blockIdx.z;
    const float* w = (z == 0) ? w0 : (z == 1) ? w1 : (z == 2) ? w2
                   : (z == 3) ? w3 : (z == 4) ? w4 : w5;
    __half* dst = (z < 3) ? g_Wh[z] : g_Vh[z - 3];
    int Ndim = (z == 5) ? 256 : 512;
    int bx = blockIdx.x * 32;  // k
    int by = blockIdx.y * 32;  // n
    if (by >= Ndim) return;
    int x = threadIdx.x, y = threadIdx.y;
#pragma unroll
    for (int i = 0; i < 32; i += 8)
        t[y + i][x] = w[(size_t)(bx + y + i) * Ndim + by + x];
    __syncthreads();
#pragma unroll
    for (int i = 0; i < 32; i += 8)
        dst[(size_t)(by + y + i) * KK + bx + x] = __float2half_rn(t[x][y + i]);
}

// ---------------- mma.sync GEMM (BK=32, static 48KB smem, 3-stage, 2 CTAs/SM) ----------------
__device__ __forceinline__ void load_tiles(
    uint32_t sa, uint32_t sb,
    const __half* __restrict__ A, const __half* __restrict__ W,
    int mBase, int M, int nBase, int kk, int tid)
{
#pragma unroll
    for (int i = 0; i < 2; i++) {
        int idx = i * 256 + tid;
        int row = idx >> 2, cu = idx & 3;
        int grow = mBase + row;
        const char* src = (const char*)(A + (size_t)grow * KK + kk) + cu * 16;
        cpa16(sa + sw64(row * 64 + cu * 16), src, grow < M);
    }
#pragma unroll
    for (int i = 0; i < 2; i++) {
        int idx = i * 256 + tid;
        int row = idx >> 2, cu = idx & 3;
        const char* src = (const char*)(W + (size_t)(nBase + row) * KK + kk) + cu * 16;
        cpa16(sb + sw64(row * 64 + cu * 16), src, true);
    }
}

// MODE 0: bias+relu -> fp16 H ; MODE 1: bias -> fp16 Y + fused BN stats ; MODE 2: bias -> fp32 out
template <int MODE>
__global__ void __launch_bounds__(256, 2) gemm_mma(
    const __half* __restrict__ Ah, const __half* __restrict__ Wt,
    const float* __restrict__ bias,
    float* __restrict__ Cf, __half* __restrict__ Ch,
    float* __restrict__ stats,
    int M, int Ncols)
{
    __shared__ __align__(1024) uint8_t smem[3 * 16384];  // 3 stages x (A 8K + B 8K)
    uint32_t sbase = smem_u32(smem);

    const int tid = threadIdx.x, lane = tid & 31, wid = tid >> 5;
    const int wm = wid >> 1, wn = wid & 1;
    const int mBase = blockIdx.y * BM;
    const int nBase = blockIdx.x * BNT;

    float acc[2][8][4];
#pragma unroll
    for (int a = 0; a < 2; a++)
#pragma unroll
        for (int b = 0; b < 8; b++)
#pragma unroll
            for (int c = 0; c < 4; c++) acc[a][b][c] = 0.f;

    load_tiles(sbase, sbase + 8192, Ah, Wt, mBase, M, nBase, 0, tid);
    cpa_commit();
    load_tiles(sbase + 16384, sbase + 16384 + 8192, Ah, Wt, mBase, M, nBase, 32, tid);
    cpa_commit();

    for (int kc = 0; kc < NCH; kc++) {
        int buf = kc % 3;
        if (kc + 1 < NCH) cpa_wait<1>();
        else              cpa_wait<0>();
        __syncthreads();
        if (kc + 2 < NCH) {
            int nb = (kc + 2) % 3;
            load_tiles(sbase + nb * 16384, sbase + nb * 16384 + 8192,
                       Ah, Wt, mBase, M, nBase, (kc + 2) * 32, tid);
            cpa_commit();
        }

        uint32_t aT = sbase + buf * 16384;
        uint32_t bT = aT + 8192;
#pragma unroll
        for (int k16 = 0; k16 < 2; k16++) {
            uint32_t aF[2][4];
#pragma unroll
            for (int fm = 0; fm < 2; fm++) {
                int row = wm * 32 + fm * 16 + (lane & 15);
                int cu = 2 * k16 + (lane >> 4);
                ldmx4(aF[fm], aT + sw64(row * 64 + cu * 16));
            }
            uint32_t bF[4][4];
#pragma unroll
            for (int g = 0; g < 4; g++) {
                int half = (lane >> 3) & 1;
                int sel = lane >> 4;
                int row = wn * 64 + g * 16 + sel * 8 + (lane & 7);
                int cu = 2 * k16 + half;
                ldmx4(bF[g], bT + sw64(row * 64 + cu * 16));
            }
#pragma unroll
            for (int fm = 0; fm < 2; fm++)
#pragma unroll
                for (int fn = 0; fn < 8; fn++)
                    mma16816(acc[fm][fn], aF[fm], &bF[fn >> 1][(fn & 1) * 2]);
        }
    }

    // ---- epilogue ----
    float* ss = (float*)smem;  // MODE 1: [0:128] col sums, [128:256] col sumsq
    if (MODE == 1) {
        __syncthreads();
        if (tid < 128) { ss[tid] = 0.f; ss[128 + tid] = 0.f; }
        __syncthreads();
    }

#pragma unroll
    for (int fn = 0; fn < 8; fn++) {
        int col = nBase + wn * 64 + fn * 8 + (lane & 3) * 2;
        float bv0 = __ldg(bias + col);
        float bv1 = __ldg(bias + col + 1);
        float ls0 = 0.f, ls1 = 0.f, lq0 = 0.f, lq1 = 0.f;
#pragma unroll
        for (int fm = 0; fm < 2; fm++) {
            int rowb = mBase + wm * 32 + fm * 16 + (lane >> 2);
            float* a = acc[fm][fn];
#pragma unroll
            for (int h = 0; h < 2; h++) {
                int r = rowb + 8 * h;
                if (r < M) {
                    float v0 = a[2 * h] + bv0, v1 = a[2 * h + 1] + bv1;
                    if (MODE == 0) {
                        v0 = fmaxf(v0, 0.f);
                        v1 = fmaxf(v1, 0.f);
                        __half2 hp = __floats2half2_rn(v0, v1);
                        *(__half2*)(Ch + (size_t)r * Ncols + col) = hp;
                    } else if (MODE == 1) {
                        __half2 hp = __floats2half2_rn(v0, v1);
                        *(__half2*)(Ch + (size_t)r * Ncols + col) = hp;
                        ls0 += v0; lq0 += v0 * v0;
                        ls1 += v1; lq1 += v1 * v1;
                    } else {
                        float2 o; o.x = v0; o.y = v1;
                        *(float2*)(Cf + (size_t)r * Ncols + col) = o;
                    }
                }
            }
        }
        if (MODE == 1) {
#pragma unroll
            for (int o = 4; o < 32; o <<= 1) {
                ls0 += __shfl_down_sync(0xffffffffu, ls0, o);
                ls1 += __shfl_down_sync(0xffffffffu, ls1, o);
                lq0 += __shfl_down_sync(0xffffffffu, lq0, o);
                lq1 += __shfl_down_sync(0xffffffffu, lq1, o);
            }
            if (lane < 4) {
                int lc = wn * 64 + fn * 8 + lane * 2;
                atomicAdd(&ss[lc], ls0);
                atomicAdd(&ss[lc + 1], ls1);
                atomicAdd(&ss[128 + lc], lq0);
                atomicAdd(&ss[128 + lc + 1], lq1);
            }
        }
    }

    if (MODE == 1) {
        __syncthreads();
        if (tid < 128) {
            atomicAdd(&stats[nBase + tid], ss[tid]);
            atomicAdd(&stats[HH + nBase + tid], ss[128 + tid]);
        }
    }
}

// ---------------- driver ----------------
extern "C" void kernel_launch(void* const* d_in, const int* in_sizes, int n_in,
                              void* d_out, int out_size) {
    const int*   xi  = (const int*)d_in[0];
    const int*   ei  = (const int*)d_in[1];
    const float* emb = (const float*)d_in[2];
    const float* w1[3] = {(const float*)d_in[3], (const float*)d_in[9],  (const float*)d_in[15]};
    const float* b1[3] = {(const float*)d_in[4], (const float*)d_in[10], (const float*)d_in[16]};
    const float* w2[3] = {(const float*)d_in[5], (const float*)d_in[11], (const float*)d_in[17]};
    const float* b2[3] = {(const float*)d_in[6], (const float*)d_in[12], (const float*)d_in[18]};
    const float* gam[2] = {(const float*)d_in[7], (const float*)d_in[13]};
    const float* bet[2] = {(const float*)d_in[8], (const float*)d_in[14]};

    __half *pSh, *pHh, *pWh, *pVh, *pYh;
    float *pStats;
    cudaGetSymbolAddress((void**)&pSh, g_Sh);
    cudaGetSymbolAddress((void**)&pHh, g_Hh);
    cudaGetSymbolAddress((void**)&pWh, g_Wh);
    cudaGetSymbolAddress((void**)&pVh, g_Vh);
    cudaGetSymbolAddress((void**)&pYh, g_Y);
    cudaGetSymbolAddress((void**)&pStats, g_stats);

    dim3 tb(32, 8);

    // front matter: all transposes (1 launch), emb convert, zero-all
    wsplit_all_k<<<dim3(16, 16, 6), tb>>>(w1[0], w1[1], w1[2], w2[0], w2[1], w2[2]);
    conv_emb_k<<<(NN * KK / 4 + 255) / 256, 256>>>(emb);
    zero_all_k<<<(NN + 255) / 256, 256>>>();
    count_deg_k<<<(EE + 255) / 256, 256>>>(ei);
    scan_k<<<1, 1024>>>();
    fill_col_k<<<(EE + 255) / 256, 256>>>(ei);

    dim3 gg512(512 / BNT, (NN + BM - 1) / BM);
    dim3 gg256(256 / BNT, (NN + BM - 1) / BM);

    for (int l = 0; l < 3; ++l) {
        if (l == 0) agg_emb_k<<<NN, 128>>>(xi);
        else        agg_bn_k<<<NN, 128>>>(pStats + (size_t)(l - 1) * 2 * HH, gam[l - 1], bet[l - 1]);

        gemm_mma<0><<<gg512, 256>>>(pSh,
            pWh + (size_t)l * KK * HH, b1[l], nullptr, pHh, nullptr, NN, 512);

        if (l < 2) {
            gemm_mma<1><<<gg512, 256>>>(pHh,
                pVh + (size_t)l * KK * HH, b2[l], nullptr, pYh,
                pStats + (size_t)l * 2 * HH, NN, 512);
        } else {
            gemm_mma<2><<<gg256, 256>>>(pHh,
                pVh + (size_t)2 * KK * HH, b2[2], (float*)d_out, nullptr, nullptr, NN, 256);
        }
    }
}